// round 5
// baseline (speedup 1.0000x reference)
#include <cuda_runtime.h>
#include <cuda_bf16.h>
#include <stdint.h>

// Problem constants (from reference): B=4, N=65536, NV=1, E=128, NH=7
#define B_  4
#define N_  65536
#define NH_ 7
#define E_  128
#define EV4 (E_ / 4)          // 32 float4 per row
#define PF_BYTES 4096         // per-block L2 prefetch slice: 32768 blocks * 4KB = 128MB = |x|
#define PF_AHEAD 1024         // prefetch ~4MB ahead of the gather wave

// x_nh elements = B*N*NH*E = 234,881,024 ; mask elements = B*N*NH = 1,835,008

// One warp per (b, n). Lanes 0..6 fetch the 7 adjc entries + mask bytes in one
// coalesced access, broadcast via shfl, then 7 independent 512B row gathers
// (MLP=7). Streaming stores (.cs) keep the 939MB output evict-first in L2 so
// x stays resident. Each block also issues one cp.async.bulk.prefetch.L2 of a
// sequential 4KB slice of x (no SM delivery, no LTS->SM bytes) so the 128MB of
// compulsory DRAM reads are fetched sequentially instead of as random 512B.
__global__ void __launch_bounds__(256) gather_nh_fused_kernel(
    const float4*        __restrict__ x,        // [B, N, EV4]
    const int*           __restrict__ adjc,     // [N, NH]
    const unsigned char* __restrict__ mask_inv, // [N, NH]
    const int*           __restrict__ lidx,     // [B, N]
    const int*           __restrict__ bsi,      // [B]
    const int*           __restrict__ slvl,     // scalar
    float4*              __restrict__ out,      // [B, N, NH, EV4]
    float*               __restrict__ out_mask, // [B, N, NH]
    int                  write_mask)
{
    // Sequential L2 prefetch of x, slightly ahead of this wave (one thread/block).
    if (threadIdx.x == 0) {
        unsigned int pb = (blockIdx.x + PF_AHEAD) & (gridDim.x - 1);  // gridDim.x = 32768 (pow2)
        const char* pf = (const char*)x + (size_t)pb * PF_BYTES;
        asm volatile("cp.async.bulk.prefetch.L2.global [%0], %1;"
                     :: "l"(pf), "r"((int)PF_BYTES));
    }

    const int wg   = (blockIdx.x * blockDim.x + threadIdx.x) >> 5;  // (b,n) id
    const int lane = threadIdx.x & 31;
    if (wg >= B_ * N_) return;

    const int b = wg >> 16;        // N_ = 65536
    const int n = wg & (N_ - 1);

    const int li  = __ldg(&lidx[b * N_ + n]);
    const int off = __ldg(&bsi[b]) << (2 * __ldg(slvl));  // bsi * 4^sampled_level

    // Lanes 0..6 fetch the 7 neighbor ids (coalesced 28B) and mask bytes.
    int gi = 0;
    if (lane < NH_) {
        gi = __ldg(&adjc[li * NH_ + lane]) - off;
        if (write_mask) {
            out_mask[(size_t)wg * NH_ + lane] =
                __ldg(&mask_inv[li * NH_ + lane]) ? 1.0f : 0.0f;
        }
    }

    const float4* xb = x + (size_t)b * N_ * EV4;
    float4* ob = out + (size_t)wg * NH_ * EV4;

    // Resolve all 7 source addresses first, then front-batch 7 independent
    // LDG.128s (L2-only, no L1 allocation), then store.
    const float4* src[NH_];
    #pragma unroll
    for (int h = 0; h < NH_; h++) {
        const int g = __shfl_sync(0xffffffffu, gi, h);
        src[h] = &xb[(size_t)g * EV4 + lane];
    }

    float4 v[NH_];
    #pragma unroll
    for (int h = 0; h < NH_; h++) v[h] = __ldcg(src[h]);

    #pragma unroll
    for (int h = 0; h < NH_; h++) __stcs(&ob[h * EV4 + lane], v[h]);
}

extern "C" void kernel_launch(void* const* d_in, const int* in_sizes, int n_in,
                              void* d_out, int out_size) {
    const float4*        x        = (const float4*)d_in[0];
    const int*           adjc     = (const int*)d_in[1];
    const unsigned char* mask_inv = (const unsigned char*)d_in[2];
    const int*           lidx     = (const int*)d_in[3];
    const int*           bsi      = (const int*)d_in[4];
    const int*           slvl     = (const int*)d_in[5];
    float*               out      = (float*)d_out;

    const long long xnh_elems  = (long long)B_ * N_ * NH_ * E_;   // 234,881,024
    const long long mask_elems = (long long)B_ * N_ * NH_;        // 1,835,008
    const int write_mask = ((long long)out_size >= xnh_elems + mask_elems) ? 1 : 0;

    const int total_warps = B_ * N_;                 // 262,144
    const int warps_per_block = 256 / 32;
    const int blocks = (total_warps + warps_per_block - 1) / warps_per_block;  // 32768

    gather_nh_fused_kernel<<<blocks, 256>>>(
        x, adjc, mask_inv, lidx, bsi, slvl,
        (float4*)out, out + xnh_elems, write_mask);
}

// round 11
// speedup vs baseline: 1.0088x; 1.0088x over previous
#include <cuda_runtime.h>
#include <cuda_bf16.h>
#include <stdint.h>

// Problem constants (from reference): B=4, N=65536, NV=1, E=128, NH=7
#define B_  4
#define N_  65536
#define NH_ 7
#define E_  128
#define EV4 (E_ / 4)   // 32 float4 per row

// x_nh elements = B*N*NH*E = 234,881,024 ; mask elements = B*N*NH = 1,835,008

// One warp per (b, n). Lanes 0..6 fetch the 7 adjc entries + mask bytes in one
// coalesced access, broadcast via shfl, then 7 independent 512B row gathers
// (MLP=7). x reads use an L2 evict_last cache-hint policy so x (32MB live set
// per batch, 128MB total vs 126MB L2) stays L2-resident ACROSS graph replays;
// output stores use .cs (evict-first) so the 939MB write stream doesn't evict x.
__device__ __forceinline__ float4 ldg_evict_last(const float4* p, uint64_t pol) {
    float4 v;
    asm volatile("ld.global.nc.L2::cache_hint.v4.f32 {%0,%1,%2,%3}, [%4], %5;"
                 : "=f"(v.x), "=f"(v.y), "=f"(v.z), "=f"(v.w)
                 : "l"(p), "l"(pol));
    return v;
}

__global__ void __launch_bounds__(256) gather_nh_fused_kernel(
    const float4*        __restrict__ x,        // [B, N, EV4]
    const int*           __restrict__ adjc,     // [N, NH]
    const unsigned char* __restrict__ mask_inv, // [N, NH]
    const int*           __restrict__ lidx,     // [B, N]
    const int*           __restrict__ bsi,      // [B]
    const int*           __restrict__ slvl,     // scalar
    float4*              __restrict__ out,      // [B, N, NH, EV4]
    float*               __restrict__ out_mask, // [B, N, NH]
    int                  write_mask)
{
    const int wg   = (blockIdx.x * blockDim.x + threadIdx.x) >> 5;  // (b,n) id
    const int lane = threadIdx.x & 31;
    if (wg >= B_ * N_) return;

    const int b = wg >> 16;        // N_ = 65536
    const int n = wg & (N_ - 1);

    const int li  = __ldg(&lidx[b * N_ + n]);
    const int off = __ldg(&bsi[b]) << (2 * __ldg(slvl));  // bsi * 4^sampled_level

    // Lanes 0..6 fetch the 7 neighbor ids (coalesced 28B) and mask bytes.
    int gi = 0;
    if (lane < NH_) {
        gi = __ldg(&adjc[li * NH_ + lane]) - off;
        if (write_mask) {
            out_mask[(size_t)wg * NH_ + lane] =
                __ldg(&mask_inv[li * NH_ + lane]) ? 1.0f : 0.0f;
        }
    }

    uint64_t pol;
    asm("createpolicy.fractional.L2::evict_last.b64 %0, 1.0;" : "=l"(pol));

    const float4* xb = x + (size_t)b * N_ * EV4;
    float4* ob = out + (size_t)wg * NH_ * EV4;

    // Resolve all 7 source addresses first, then front-batch 7 independent
    // LDG.128s (L2 evict_last), then store streaming.
    const float4* src[NH_];
    #pragma unroll
    for (int h = 0; h < NH_; h++) {
        const int g = __shfl_sync(0xffffffffu, gi, h);
        src[h] = &xb[(size_t)g * EV4 + lane];
    }

    float4 v[NH_];
    #pragma unroll
    for (int h = 0; h < NH_; h++) v[h] = ldg_evict_last(src[h], pol);

    #pragma unroll
    for (int h = 0; h < NH_; h++) __stcs(&ob[h * EV4 + lane], v[h]);
}

extern "C" void kernel_launch(void* const* d_in, const int* in_sizes, int n_in,
                              void* d_out, int out_size) {
    const float4*        x        = (const float4*)d_in[0];
    const int*           adjc     = (const int*)d_in[1];
    const unsigned char* mask_inv = (const unsigned char*)d_in[2];
    const int*           lidx     = (const int*)d_in[3];
    const int*           bsi      = (const int*)d_in[4];
    const int*           slvl     = (const int*)d_in[5];
    float*               out      = (float*)d_out;

    const long long xnh_elems  = (long long)B_ * N_ * NH_ * E_;   // 234,881,024
    const long long mask_elems = (long long)B_ * N_ * NH_;        // 1,835,008
    const int write_mask = ((long long)out_size >= xnh_elems + mask_elems) ? 1 : 0;

    const int total_warps = B_ * N_;                 // 262,144
    const int warps_per_block = 256 / 32;
    const int blocks = (total_warps + warps_per_block - 1) / warps_per_block;  // 32768

    gather_nh_fused_kernel<<<blocks, 256>>>(
        x, adjc, mask_inv, lidx, bsi, slvl,
        (float4*)out, out + xnh_elems, write_mask);
}